// round 3
// baseline (speedup 1.0000x reference)
#include <cuda_runtime.h>
#include <math.h>

#define NB   4
#define SEQ  4096
#define EMB  1024
#define HID  4096
#define NTOK (NB * SEQ)   // 16384

// ---------------- device scratch (allocation-free rule: __device__ globals) ----
__device__ float g_wvs [EMB * 64];                 // folded w_v: (1024, 64)
__device__ float g_vsum[NTOK * 64];                // (16384, 64) == (1024,1024) view
__device__ float g_A   [NB * 256 * EMB];           // 1024 distinct attn_out rows
__device__ float g_h1  [(long long)NTOK * EMB];    // LN1 output (64 MB)
__device__ float g_ff1 [(long long)NTOK * HID];    // relu(h1@w_ff1+b) (256 MB)
__device__ float g_y   [(long long)NTOK * EMB];    // ff2 + h1 (64 MB)

// ---------------- fold w_v over heads: Wvs[e,d] = sum_j w_v[e, j*64+d] --------
__global__ void fold_wv_kernel(const float* __restrict__ wv) {
    int idx = blockIdx.x * blockDim.x + threadIdx.x;
    if (idx >= EMB * 64) return;
    int e = idx >> 6, d = idx & 63;
    float s = 0.f;
#pragma unroll
    for (int j = 0; j < 16; j++) s += wv[e * EMB + j * 64 + d];
    g_wvs[idx] = s;
}

// ---------------- small GEMM: C(M,64) = A(M,K) @ g_wvs(K,64) ------------------
__global__ void sgemm_n64(const float* __restrict__ A, float* __restrict__ C,
                          int M, int K) {
    const int BM = 64, BK = 16, TM = 4, TN = 4;
    __shared__ float As[BK][BM];
    __shared__ float Bs[BK][64];
    int tid = threadIdx.x;                 // 256 threads
    int by  = blockIdx.y;
    int tx = tid & 15, ty = tid >> 4;
    int aRow = tid >> 2, aCol = (tid & 3) * 4;
    int bRow = tid >> 4, bCol = (tid & 15) * 4;
    float acc[TM][TN] = {};
    const float* Ab = A + (size_t)by * BM * K;
    for (int k0 = 0; k0 < K; k0 += BK) {
        float4 a4 = *(const float4*)(Ab + (size_t)aRow * K + k0 + aCol);
        As[aCol + 0][aRow] = a4.x; As[aCol + 1][aRow] = a4.y;
        As[aCol + 2][aRow] = a4.z; As[aCol + 3][aRow] = a4.w;
        float4 b4 = *(const float4*)(g_wvs + (k0 + bRow) * 64 + bCol);
        *(float4*)&Bs[bRow][bCol] = b4;
        __syncthreads();
#pragma unroll
        for (int kk = 0; kk < BK; kk++) {
            float4 ar4 = *(const float4*)&As[kk][ty * TM];
            float4 br4 = *(const float4*)&Bs[kk][tx * TN];
            float a[4] = {ar4.x, ar4.y, ar4.z, ar4.w};
            float b[4] = {br4.x, br4.y, br4.z, br4.w};
#pragma unroll
            for (int i = 0; i < 4; i++)
#pragma unroll
                for (int j = 0; j < 4; j++) acc[i][j] += a[i] * b[j];
        }
        __syncthreads();
    }
#pragma unroll
    for (int i = 0; i < TM; i++) {
        float4 v = make_float4(acc[i][0], acc[i][1], acc[i][2], acc[i][3]);
        *(float4*)(C + (size_t)(by * BM + ty * TM + i) * 64 + tx * TN) = v;
    }
}

// ---------------- workhorse SGEMM: 128x128x8, 8x8/thread, 256 threads ---------
template <bool RELU, bool BIAS, bool RES>
__global__ __launch_bounds__(256)
void sgemm128(const float* __restrict__ A, const float* __restrict__ B,
              const float* __restrict__ bias, const float* __restrict__ res,
              float* __restrict__ C, int M, int N, int K) {
    const int BM = 128, BN = 128, BK = 8, TM = 8, TN = 8;
    __shared__ float As[BK][BM];
    __shared__ float Bs[BK][BN];
    int tid = threadIdx.x;
    int bx = blockIdx.x, by = blockIdx.y;
    int tx = tid & 15, ty = tid >> 4;      // 16 x 16 threads
    int aRow = tid >> 1,  aCol = (tid & 1) * 4;    // A tile 128x8
    int bRow = tid >> 5,  bCol = (tid & 31) * 4;   // B tile 8x128
    float acc[TM][TN] = {};
    const float* Ab = A + (size_t)by * BM * K;
    const float* Bb = B + (size_t)bx * BN;

    for (int k0 = 0; k0 < K; k0 += BK) {
        float4 a4 = *(const float4*)(Ab + (size_t)aRow * K + k0 + aCol);
        As[aCol + 0][aRow] = a4.x; As[aCol + 1][aRow] = a4.y;
        As[aCol + 2][aRow] = a4.z; As[aCol + 3][aRow] = a4.w;
        float4 b4 = *(const float4*)(Bb + (size_t)(k0 + bRow) * N + bCol);
        *(float4*)&Bs[bRow][bCol] = b4;
        __syncthreads();
#pragma unroll
        for (int kk = 0; kk < BK; kk++) {
            float4 a0 = *(const float4*)&As[kk][ty * TM];
            float4 a1 = *(const float4*)&As[kk][ty * TM + 4];
            float4 b0 = *(const float4*)&Bs[kk][tx * TN];
            float4 b1 = *(const float4*)&Bs[kk][tx * TN + 4];
            float ar[8] = {a0.x, a0.y, a0.z, a0.w, a1.x, a1.y, a1.z, a1.w};
            float br[8] = {b0.x, b0.y, b0.z, b0.w, b1.x, b1.y, b1.z, b1.w};
#pragma unroll
            for (int i = 0; i < TM; i++)
#pragma unroll
                for (int j = 0; j < TN; j++) acc[i][j] += ar[i] * br[j];
        }
        __syncthreads();
    }

    int colBase = bx * BN + tx * TN;
#pragma unroll
    for (int i = 0; i < TM; i++) {
        int row = by * BM + ty * TM + i;
        float* crow = C + (size_t)row * N + colBase;
        const float* rrow = RES ? (res + (size_t)row * N + colBase) : nullptr;
#pragma unroll
        for (int j = 0; j < TN; j += 4) {
            float4 v = make_float4(acc[i][j], acc[i][j+1], acc[i][j+2], acc[i][j+3]);
            if (BIAS) {
                float4 bv = *(const float4*)(bias + colBase + j);
                v.x += bv.x; v.y += bv.y; v.z += bv.z; v.w += bv.w;
            }
            if (RES) {
                float4 rv = *(const float4*)(rrow + j);
                v.x += rv.x; v.y += rv.y; v.z += rv.z; v.w += rv.w;
            }
            if (RELU) {
                v.x = fmaxf(v.x, 0.f); v.y = fmaxf(v.y, 0.f);
                v.z = fmaxf(v.z, 0.f); v.w = fmaxf(v.w, 0.f);
            }
            *(float4*)(crow + j) = v;
        }
    }
}

// ---------------- block reduce (sum, sumsq) over 256 threads ------------------
__device__ __forceinline__ void block_reduce2(float& s, float& q) {
#pragma unroll
    for (int off = 16; off; off >>= 1) {
        s += __shfl_xor_sync(0xffffffffu, s, off);
        q += __shfl_xor_sync(0xffffffffu, q, off);
    }
    __shared__ float sh_s[8], sh_q[8];
    int w = threadIdx.x >> 5;
    if ((threadIdx.x & 31) == 0) { sh_s[w] = s; sh_q[w] = q; }
    __syncthreads();
    s = 0.f; q = 0.f;
#pragma unroll
    for (int i = 0; i < 8; i++) { s += sh_s[i]; q += sh_q[i]; }
}

// ---------------- LN1: h1 = LayerNorm(x + A[n, l%256]) -----------------------
__global__ void ln1_kernel(const float* __restrict__ x,
                           const float* __restrict__ w, const float* __restrict__ b) {
    int t = blockIdx.x;                    // token 0..16383
    int n = t >> 12, l = t & (SEQ - 1);
    int c = threadIdx.x;                   // float4 index 0..255
    float4 xv = ((const float4*)(x + (size_t)t * EMB))[c];
    float4 av = ((const float4*)(g_A + (size_t)(n * 256 + (l & 255)) * EMB))[c];
    float v0 = xv.x + av.x, v1 = xv.y + av.y, v2 = xv.z + av.z, v3 = xv.w + av.w;
    float s = v0 + v1 + v2 + v3;
    float q = v0 * v0 + v1 * v1 + v2 * v2 + v3 * v3;
    block_reduce2(s, q);
    float mu  = s * (1.f / EMB);
    float var = q * (1.f / EMB) - mu * mu;
    float rs  = rsqrtf(var + 1e-5f);
    float4 wv = ((const float4*)w)[c], bv = ((const float4*)b)[c];
    float4 o;
    o.x = (v0 - mu) * rs * wv.x + bv.x;
    o.y = (v1 - mu) * rs * wv.y + bv.y;
    o.z = (v2 - mu) * rs * wv.z + bv.z;
    o.w = (v3 - mu) * rs * wv.w + bv.w;
    ((float4*)(g_h1 + (size_t)t * EMB))[c] = o;
}

// ---------------- LN2: out = LayerNorm(y)  (y already = ff2 + h1) -------------
__global__ void ln2_kernel(const float* __restrict__ w, const float* __restrict__ b,
                           float* __restrict__ out) {
    int t = blockIdx.x;
    int c = threadIdx.x;
    float4 yv = ((const float4*)(g_y + (size_t)t * EMB))[c];
    float v0 = yv.x, v1 = yv.y, v2 = yv.z, v3 = yv.w;
    float s = v0 + v1 + v2 + v3;
    float q = v0 * v0 + v1 * v1 + v2 * v2 + v3 * v3;
    block_reduce2(s, q);
    float mu  = s * (1.f / EMB);
    float var = q * (1.f / EMB) - mu * mu;
    float rs  = rsqrtf(var + 1e-5f);
    float4 wv = ((const float4*)w)[c], bv = ((const float4*)b)[c];
    float4 o;
    o.x = (v0 - mu) * rs * wv.x + bv.x;
    o.y = (v1 - mu) * rs * wv.y + bv.y;
    o.z = (v2 - mu) * rs * wv.z + bv.z;
    o.w = (v3 - mu) * rs * wv.w + bv.w;
    ((float4*)(out + (size_t)t * EMB))[c] = o;
}

// ------------------------------------------------------------------------------
extern "C" void kernel_launch(void* const* d_in, const int* in_sizes, int n_in,
                              void* d_out, int out_size) {
    const float* x     = (const float*)d_in[0];
    const float* w_v   = (const float*)d_in[3];
    const float* w_o   = (const float*)d_in[4];
    const float* b_o   = (const float*)d_in[5];
    const float* ln1_w = (const float*)d_in[6];
    const float* ln1_b = (const float*)d_in[7];
    const float* ln2_w = (const float*)d_in[8];
    const float* ln2_b = (const float*)d_in[9];
    const float* w_ff1 = (const float*)d_in[10];
    const float* b_ff1 = (const float*)d_in[11];
    const float* w_ff2 = (const float*)d_in[12];
    const float* b_ff2 = (const float*)d_in[13];
    float* out = (float*)d_out;

    float *vsum, *A, *h1, *ff1, *y;
    cudaGetSymbolAddress((void**)&vsum, g_vsum);
    cudaGetSymbolAddress((void**)&A,    g_A);
    cudaGetSymbolAddress((void**)&h1,   g_h1);
    cudaGetSymbolAddress((void**)&ff1,  g_ff1);
    cudaGetSymbolAddress((void**)&y,    g_y);

    // 1) fold w_v over heads -> (1024, 64)
    fold_wv_kernel<<<(EMB * 64 + 255) / 256, 256>>>(w_v);

    // 2) Vsum = x @ Wvs : (16384,1024)@(1024,64)
    sgemm_n64<<<dim3(1, NTOK / 64), 256>>>(x, vsum, NTOK, EMB);

    // 3) A = Vsum.view(1024,1024) @ w_o + b_o  (the only 1024 distinct attn rows)
    sgemm128<false, true, false><<<dim3(EMB / 128, 1024 / 128), 256>>>(
        vsum, w_o, b_o, nullptr, A, 1024, EMB, EMB);

    // 4) h1 = LN1(x + A[n, l%256])
    ln1_kernel<<<NTOK, 256>>>(x, ln1_w, ln1_b);

    // 5) ff1 = relu(h1 @ w_ff1 + b_ff1) : (16384,1024)@(1024,4096)
    sgemm128<true, true, false><<<dim3(HID / 128, NTOK / 128), 256>>>(
        h1, w_ff1, b_ff1, nullptr, ff1, NTOK, HID, EMB);

    // 6) y = ff1 @ w_ff2 + b_ff2 + h1 : (16384,4096)@(4096,1024)
    sgemm128<false, true, true><<<dim3(EMB / 128, NTOK / 128), 256>>>(
        ff1, w_ff2, b_ff2, h1, y, NTOK, EMB, HID);

    // 7) out = LN2(y)
    ln2_kernel<<<NTOK, 256>>>(ln2_w, ln2_b, out);
}

// round 5
// speedup vs baseline: 2.3273x; 2.3273x over previous
#include <cuda_runtime.h>
#include <cuda_bf16.h>
#include <cstdint>
#include <math.h>

#define NB   4
#define SEQ  4096
#define EMB  1024
#define HID  4096
#define NTOK (NB * SEQ)   // 16384

// ======================= helpers ==============================================
__device__ __forceinline__ uint32_t smem_u32(const void* p) {
    uint32_t a;
    asm("{ .reg .u64 t; cvta.to.shared.u64 t, %1; cvt.u32.u64 %0, t; }" : "=r"(a) : "l"(p));
    return a;
}
// SW64 swizzle for 64-byte rows: granule ^= (row>>1)&3 — conflict-free for
// 16B cp.async stores AND ldmatrix reads (even/odd rows live on opposite
// 16-bank halves; within a half the xor makes the 4 granules distinct).
__device__ __forceinline__ uint32_t swz64(uint32_t o) { return o ^ ((o >> 3) & 0x30); }

__device__ __forceinline__ void cp_async16(uint32_t dst, const void* src) {
    asm volatile("cp.async.cg.shared.global [%0], [%1], 16;" :: "r"(dst), "l"(src));
}
#define CP_COMMIT() asm volatile("cp.async.commit_group;" ::: "memory")
#define CP_WAIT2()  asm volatile("cp.async.wait_group 2;" ::: "memory")

__device__ __forceinline__ void ldmx4(uint32_t r[4], uint32_t addr) {
    asm volatile("ldmatrix.sync.aligned.m8n8.x4.shared.b16 {%0,%1,%2,%3}, [%4];"
                 : "=r"(r[0]), "=r"(r[1]), "=r"(r[2]), "=r"(r[3]) : "r"(addr));
}
__device__ __forceinline__ void mma16816(float d[4], const uint32_t a[4],
                                         uint32_t b0, uint32_t b1) {
    asm volatile("mma.sync.aligned.m16n8k16.row.col.f32.bf16.bf16.f32 "
                 "{%0,%1,%2,%3}, {%4,%5,%6,%7}, {%8,%9}, {%0,%1,%2,%3};"
                 : "+f"(d[0]), "+f"(d[1]), "+f"(d[2]), "+f"(d[3])
                 : "r"(a[0]), "r"(a[1]), "r"(a[2]), "r"(a[3]), "r"(b0), "r"(b1));
}

__device__ __forceinline__ void cvt_hilo(float x, __nv_bfloat16& h, __nv_bfloat16& l) {
    h = __float2bfloat16(x);
    l = __float2bfloat16(x - __bfloat162float(h));
}

// ======================= device scratch =======================================
__device__ float g_wvs [EMB * 64];
__device__ float g_vsum[NTOK * 64];
__device__ float g_A   [NB * 256 * EMB];
__device__ float g_h1  [(long long)NTOK * EMB];                 // fp32 residual
__device__ __align__(16) __nv_bfloat16 g_h1h[(long long)NTOK * EMB];
__device__ __align__(16) __nv_bfloat16 g_h1l[(long long)NTOK * EMB];
__device__ __align__(16) __nv_bfloat16 g_ff1h[(long long)NTOK * HID];
__device__ __align__(16) __nv_bfloat16 g_ff1l[(long long)NTOK * HID];
__device__ __align__(16) __nv_bfloat16 g_w1t_h[(long long)HID * EMB];  // w_ff1^T
__device__ __align__(16) __nv_bfloat16 g_w1t_l[(long long)HID * EMB];
__device__ __align__(16) __nv_bfloat16 g_w2t_h[(long long)EMB * HID];  // w_ff2^T
__device__ __align__(16) __nv_bfloat16 g_w2t_l[(long long)EMB * HID];
__device__ float g_y   [(long long)NTOK * EMB];

// ======================= fold w_v over heads ==================================
__global__ void fold_wv_kernel(const float* __restrict__ wv) {
    int idx = blockIdx.x * blockDim.x + threadIdx.x;
    if (idx >= EMB * 64) return;
    int e = idx >> 6, d = idx & 63;
    float s = 0.f;
#pragma unroll
    for (int j = 0; j < 16; j++) s += wv[e * EMB + j * 64 + d];
    g_wvs[idx] = s;
}

// ============== transpose + bf16 hi/lo convert: src(R,C) -> dst(C,R) ==========
__global__ void transpose_cvt(const float* __restrict__ src,
                              __nv_bfloat16* __restrict__ dh,
                              __nv_bfloat16* __restrict__ dl, int R, int C) {
    __shared__ float tile[32][33];
    int r = blockIdx.y * 32 + threadIdx.y;
    int c = blockIdx.x * 32 + threadIdx.x;
    tile[threadIdx.y][threadIdx.x] = src[(size_t)r * C + c];
    __syncthreads();
    int orow = blockIdx.x * 32 + threadIdx.y;
    int ocol = blockIdx.y * 32 + threadIdx.x;
    float v = tile[threadIdx.x][threadIdx.y];
    __nv_bfloat16 h, l;
    cvt_hilo(v, h, l);
    dh[(size_t)orow * R + ocol] = h;
    dl[(size_t)orow * R + ocol] = l;
}

// =================== small GEMM: C(M,64) = A(M,K) @ g_wvs(K,64) ===============
__global__ void sgemm_n64(const float* __restrict__ A, float* __restrict__ C,
                          int M, int K) {
    const int BM = 64, BK = 16, TM = 4, TN = 4;
    __shared__ float As[BK][BM];
    __shared__ float Bs[BK][64];
    int tid = threadIdx.x;
    int by  = blockIdx.y;
    int tx = tid & 15, ty = tid >> 4;
    int aRow = tid >> 2, aCol = (tid & 3) * 4;
    int bRow = tid >> 4, bCol = (tid & 15) * 4;
    float acc[TM][TN] = {};
    const float* Ab = A + (size_t)by * BM * K;
    for (int k0 = 0; k0 < K; k0 += BK) {
        float4 a4 = *(const float4*)(Ab + (size_t)aRow * K + k0 + aCol);
        As[aCol + 0][aRow] = a4.x; As[aCol + 1][aRow] = a4.y;
        As[aCol + 2][aRow] = a4.z; As[aCol + 3][aRow] = a4.w;
        float4 b4 = *(const float4*)(g_wvs + (k0 + bRow) * 64 + bCol);
        *(float4*)&Bs[bRow][bCol] = b4;
        __syncthreads();
#pragma unroll
        for (int kk = 0; kk < BK; kk++) {
            float4 ar4 = *(const float4*)&As[kk][ty * TM];
            float4 br4 = *(const float4*)&Bs[kk][tx * TN];
            float a[4] = {ar4.x, ar4.y, ar4.z, ar4.w};
            float b[4] = {br4.x, br4.y, br4.z, br4.w};
#pragma unroll
            for (int i = 0; i < 4; i++)
#pragma unroll
                for (int j = 0; j < 4; j++) acc[i][j] += a[i] * b[j];
        }
        __syncthreads();
    }
#pragma unroll
    for (int i = 0; i < TM; i++) {
        float4 v = make_float4(acc[i][0], acc[i][1], acc[i][2], acc[i][3]);
        *(float4*)(C + (size_t)(by * BM + ty * TM + i) * 64 + tx * TN) = v;
    }
}

// ============== fp32 SIMT GEMM (small 1024^3 A-GEMM) ==========================
template <bool RELU, bool BIAS, bool RES>
__global__ __launch_bounds__(256)
void sgemm128(const float* __restrict__ A, const float* __restrict__ B,
              const float* __restrict__ bias, const float* __restrict__ res,
              float* __restrict__ C, int M, int N, int K) {
    const int BM = 128, BN = 128, BK = 8, TM = 8, TN = 8;
    __shared__ float As[BK][BM];
    __shared__ float Bs[BK][BN];
    int tid = threadIdx.x;
    int bx = blockIdx.x, by = blockIdx.y;
    int tx = tid & 15, ty = tid >> 4;
    int aRow = tid >> 1,  aCol = (tid & 1) * 4;
    int bRow = tid >> 5,  bCol = (tid & 31) * 4;
    float acc[TM][TN] = {};
    const float* Ab = A + (size_t)by * BM * K;
    const float* Bb = B + (size_t)bx * BN;

    for (int k0 = 0; k0 < K; k0 += BK) {
        float4 a4 = *(const float4*)(Ab + (size_t)aRow * K + k0 + aCol);
        As[aCol + 0][aRow] = a4.x; As[aCol + 1][aRow] = a4.y;
        As[aCol + 2][aRow] = a4.z; As[aCol + 3][aRow] = a4.w;
        float4 b4 = *(const float4*)(Bb + (size_t)(k0 + bRow) * N + bCol);
        *(float4*)&Bs[bRow][bCol] = b4;
        __syncthreads();
#pragma unroll
        for (int kk = 0; kk < BK; kk++) {
            float4 a0 = *(const float4*)&As[kk][ty * TM];
            float4 a1 = *(const float4*)&As[kk][ty * TM + 4];
            float4 b0 = *(const float4*)&Bs[kk][tx * TN];
            float4 b1 = *(const float4*)&Bs[kk][tx * TN + 4];
            float ar[8] = {a0.x, a0.y, a0.z, a0.w, a1.x, a1.y, a1.z, a1.w};
            float br[8] = {b0.x, b0.y, b0.z, b0.w, b1.x, b1.y, b1.z, b1.w};
#pragma unroll
            for (int i = 0; i < TM; i++)
#pragma unroll
                for (int j = 0; j < TN; j++) acc[i][j] += ar[i] * br[j];
        }
        __syncthreads();
    }

    int colBase = bx * BN + tx * TN;
#pragma unroll
    for (int i = 0; i < TM; i++) {
        int row = by * BM + ty * TM + i;
        float* crow = C + (size_t)row * N + colBase;
        const float* rrow = RES ? (res + (size_t)row * N + colBase) : nullptr;
#pragma unroll
        for (int j = 0; j < TN; j += 4) {
            float4 v = make_float4(acc[i][j], acc[i][j+1], acc[i][j+2], acc[i][j+3]);
            if (BIAS) {
                float4 bv = *(const float4*)(bias + colBase + j);
                v.x += bv.x; v.y += bv.y; v.z += bv.z; v.w += bv.w;
            }
            if (RES) {
                float4 rv = *(const float4*)(rrow + j);
                v.x += rv.x; v.y += rv.y; v.z += rv.z; v.w += rv.w;
            }
            if (RELU) {
                v.x = fmaxf(v.x, 0.f); v.y = fmaxf(v.y, 0.f);
                v.z = fmaxf(v.z, 0.f); v.w = fmaxf(v.w, 0.f);
            }
            *(float4*)(crow + j) = v;
        }
    }
}

// ================= HMMA bf16 hi/lo-split GEMM (non-'a' tensor path) ===========
// C = A(M,K) @ B(N,K)^T. A,B as bf16 hi/lo. CTA tile 128x128x32, 8 warps (2x4),
// warp tile 64x32. 3-stage cp.async pipeline; stage = Ah|Al|Bh|Bl, 8KB each.
// G1: out = relu(C+bias) -> bf16 hi/lo.   G2: out = C+bias+res -> fp32.
#define STG_BYTES 32768
template <bool G1>
__global__ __launch_bounds__(256, 1)
void gemm_mma(const __nv_bfloat16* __restrict__ Ah, const __nv_bfloat16* __restrict__ Al,
              const __nv_bfloat16* __restrict__ Bh, const __nv_bfloat16* __restrict__ Bl,
              const float* __restrict__ bias, const float* __restrict__ res,
              __nv_bfloat16* __restrict__ Oh, __nv_bfloat16* __restrict__ Ol,
              float* __restrict__ Of, int K, int N) {
    extern __shared__ char smem[];
    const uint32_t sb = smem_u32(smem);
    const int tid  = threadIdx.x;
    const int lane = tid & 31;
    const int wid  = tid >> 5;
    const int wm = wid >> 2;          // 0..1  (64-row slab)
    const int wn = wid & 3;           // 0..3  (32-col slab)
    const int bx = blockIdx.x, by = blockIdx.y;

    // ---- loader mapping: 2 chunks (rows r, r+64) x 4 tiles per thread -------
    const int lr = tid >> 2, lg = tid & 3;
    const uint32_t sd0 = lr * 64 + ((lg ^ ((lr >> 1) & 3)) << 4);
    const uint32_t sd1 = (lr + 64) * 64 + ((lg ^ (((lr + 64) >> 1) & 3)) << 4);
    const size_t arow0 = (size_t)(by * 128 + lr) * K;
    const size_t arow1 = (size_t)(by * 128 + lr + 64) * K;
    const size_t brow0 = (size_t)(bx * 128 + lr) * K;
    const size_t brow1 = (size_t)(bx * 128 + lr + 64) * K;
    const int kel = lg * 8;            // element offset of this 16B granule

    const int NC = K / 32;
    auto load_stage = [&](int c, int s) {
        const uint32_t st = sb + s * STG_BYTES;
        const int kc = c * 32 + kel;
        cp_async16(st +         sd0, Ah + arow0 + kc);
        cp_async16(st +         sd1, Ah + arow1 + kc);
        cp_async16(st +  8192 + sd0, Al + arow0 + kc);
        cp_async16(st +  8192 + sd1, Al + arow1 + kc);
        cp_async16(st + 16384 + sd0, Bh + brow0 + kc);
        cp_async16(st + 16384 + sd1, Bh + brow1 + kc);
        cp_async16(st + 24576 + sd0, Bl + brow0 + kc);
        cp_async16(st + 24576 + sd1, Bl + brow1 + kc);
        CP_COMMIT();
    };

    load_stage(0, 0); load_stage(1, 1); load_stage(2, 2);

    // ---- ldmatrix lane addressing (byte offsets before swizzle) -------------
    const int lr8 = lane & 7, l8 = (lane >> 3) & 1, l16 = (lane >> 4) & 1;
    const int frow = lr8 + l8 * 8;          // row within a 16-row tile
    const int fkb  = l16 * 16;              // 0 or 16 bytes into the k16 step

    float acc[4][4][4] = {};

    for (int c = 0; c < NC; c++) {
        const int s = c % 3;
        CP_WAIT2();
        __syncthreads();
        const uint32_t st = sb + s * STG_BYTES;
#pragma unroll
        for (int ks = 0; ks < 2; ks++) {
            const int kb = ks * 32 + fkb;
            uint32_t ah[4][4], al[4][4], bh[4][2], bl[4][2];
#pragma unroll
            for (int mi = 0; mi < 4; mi++) {
                const uint32_t off = swz64((wm * 64 + mi * 16 + frow) * 64 + kb);
                ldmx4(ah[mi], st + off);
                ldmx4(al[mi], st + 8192 + off);
            }
#pragma unroll
            for (int nt = 0; nt < 2; nt++) {
                const uint32_t off = swz64((wn * 32 + nt * 16 + frow) * 64 + kb);
                uint32_t q[4];
                ldmx4(q, st + 16384 + off);
                bh[nt*2][0] = q[0]; bh[nt*2+1][0] = q[1];
                bh[nt*2][1] = q[2]; bh[nt*2+1][1] = q[3];
                ldmx4(q, st + 24576 + off);
                bl[nt*2][0] = q[0]; bl[nt*2+1][0] = q[1];
                bl[nt*2][1] = q[2]; bl[nt*2+1][1] = q[3];
            }
#pragma unroll
            for (int mi = 0; mi < 4; mi++)
#pragma unroll
                for (int j = 0; j < 4; j++) {
                    mma16816(acc[mi][j], ah[mi], bh[j][0], bh[j][1]);
                    mma16816(acc[mi][j], ah[mi], bl[j][0], bl[j][1]);
                    mma16816(acc[mi][j], al[mi], bh[j][0], bh[j][1]);
                }
        }
        __syncthreads();
        if (c + 3 < NC) load_stage(c + 3, s);
    }

    // ---- epilogue: thread holds (row g, g+8) x col tg*2 per (mi,j) tile -----
    const int g = lane >> 2, tg = lane & 3;
#pragma unroll
    for (int mi = 0; mi < 4; mi++) {
#pragma unroll
        for (int j = 0; j < 4; j++) {
            const int col = bx * 128 + wn * 32 + j * 8 + tg * 2;
            const float2 b2 = *(const float2*)(bias + col);
#pragma unroll
            for (int hrow = 0; hrow < 2; hrow++) {
                const size_t row = (size_t)(by * 128 + wm * 64 + mi * 16 + g + hrow * 8);
                float v0 = acc[mi][j][hrow * 2 + 0] + b2.x;
                float v1 = acc[mi][j][hrow * 2 + 1] + b2.y;
                if (G1) {
                    v0 = fmaxf(v0, 0.f); v1 = fmaxf(v1, 0.f);
                    __nv_bfloat16 h0, l0, h1, l1;
                    cvt_hilo(v0, h0, l0); cvt_hilo(v1, h1, l1);
                    __nv_bfloat162 hh; hh.x = h0; hh.y = h1;
                    __nv_bfloat162 ll; ll.x = l0; ll.y = l1;
                    *(__nv_bfloat162*)(Oh + row * N + col) = hh;
                    *(__nv_bfloat162*)(Ol + row * N + col) = ll;
                } else {
                    const float2 rv = *(const float2*)(res + row * N + col);
                    float2 o = make_float2(v0 + rv.x, v1 + rv.y);
                    *(float2*)(Of + row * N + col) = o;
                }
            }
        }
    }
}

// ======================= LayerNorm kernels ====================================
__device__ __forceinline__ void block_reduce2(float& s, float& q) {
#pragma unroll
    for (int off = 16; off; off >>= 1) {
        s += __shfl_xor_sync(0xffffffffu, s, off);
        q += __shfl_xor_sync(0xffffffffu, q, off);
    }
    __shared__ float sh_s[8], sh_q[8];
    int w = threadIdx.x >> 5;
    if ((threadIdx.x & 31) == 0) { sh_s[w] = s; sh_q[w] = q; }
    __syncthreads();
    s = 0.f; q = 0.f;
#pragma unroll
    for (int i = 0; i < 8; i++) { s += sh_s[i]; q += sh_q[i]; }
}

__global__ void ln1_kernel(const float* __restrict__ x,
                           const float* __restrict__ w, const float* __restrict__ b) {
    int t = blockIdx.x;
    int n = t >> 12, l = t & (SEQ - 1);
    int c = threadIdx.x;
    float4 xv = ((const float4*)(x + (size_t)t * EMB))[c];
    float4 av = ((const float4*)(g_A + (size_t)(n * 256 + (l & 255)) * EMB))[c];
    float v0 = xv.x + av.x, v1 = xv.y + av.y, v2 = xv.z + av.z, v3 = xv.w + av.w;
    float s = v0 + v1 + v2 + v3;
    float q = v0 * v0 + v1 * v1 + v2 * v2 + v3 * v3;
    block_reduce2(s, q);
    float mu  = s * (1.f / EMB);
    float var = q * (1.f / EMB) - mu * mu;
    float rs  = rsqrtf(var + 1e-5f);
    float4 wv = ((const float4*)w)[c], bv = ((const float4*)b)[c];
    float4 o;
    o.x = (v0 - mu) * rs * wv.x + bv.x;
    o.y = (v1 - mu) * rs * wv.y + bv.y;
    o.z = (v2 - mu) * rs * wv.z + bv.z;
    o.w = (v3 - mu) * rs * wv.w + bv.w;
    ((float4*)(g_h1 + (size_t)t * EMB))[c] = o;
    __align__(8) __nv_bfloat16 h4[4], l4[4];
    cvt_hilo(o.x, h4[0], l4[0]); cvt_hilo(o.y, h4[1], l4[1]);
    cvt_hilo(o.z, h4[2], l4[2]); cvt_hilo(o.w, h4[3], l4[3]);
    ((uint2*)(g_h1h + (size_t)t * EMB))[c] = *(uint2*)h4;
    ((uint2*)(g_h1l + (size_t)t * EMB))[c] = *(uint2*)l4;
}

__global__ void ln2_kernel(const float* __restrict__ w, const float* __restrict__ b,
                           float* __restrict__ out) {
    int t = blockIdx.x;
    int c = threadIdx.x;
    float4 yv = ((const float4*)(g_y + (size_t)t * EMB))[c];
    float v0 = yv.x, v1 = yv.y, v2 = yv.z, v3 = yv.w;
    float s = v0 + v1 + v2 + v3;
    float q = v0 * v0 + v1 * v1 + v2 * v2 + v3 * v3;
    block_reduce2(s, q);
    float mu  = s * (1.f / EMB);
    float var = q * (1.f / EMB) - mu * mu;
    float rs  = rsqrtf(var + 1e-5f);
    float4 wv = ((const float4*)w)[c], bv = ((const float4*)b)[c];
    float4 o;
    o.x = (v0 - mu) * rs * wv.x + bv.x;
    o.y = (v1 - mu) * rs * wv.y + bv.y;
    o.z = (v2 - mu) * rs * wv.z + bv.z;
    o.w = (v3 - mu) * rs * wv.w + bv.w;
    ((float4*)(out + (size_t)t * EMB))[c] = o;
}

// ==============================================================================
extern "C" void kernel_launch(void* const* d_in, const int* in_sizes, int n_in,
                              void* d_out, int out_size) {
    const float* x     = (const float*)d_in[0];
    const float* w_v   = (const float*)d_in[3];
    const float* w_o   = (const float*)d_in[4];
    const float* b_o   = (const float*)d_in[5];
    const float* ln1_w = (const float*)d_in[6];
    const float* ln1_b = (const float*)d_in[7];
    const float* ln2_w = (const float*)d_in[8];
    const float* ln2_b = (const float*)d_in[9];
    const float* w_ff1 = (const float*)d_in[10];
    const float* b_ff1 = (const float*)d_in[11];
    const float* w_ff2 = (const float*)d_in[12];
    const float* b_ff2 = (const float*)d_in[13];
    float* out = (float*)d_out;

    float *vsum, *A, *h1, *y;
    __nv_bfloat16 *h1h, *h1l, *ff1h, *ff1l, *w1h, *w1l, *w2h, *w2l;
    cudaGetSymbolAddress((void**)&vsum, g_vsum);
    cudaGetSymbolAddress((void**)&A,    g_A);
    cudaGetSymbolAddress((void**)&h1,   g_h1);
    cudaGetSymbolAddress((void**)&y,    g_y);
    cudaGetSymbolAddress((void**)&h1h,  g_h1h);
    cudaGetSymbolAddress((void**)&h1l,  g_h1l);
    cudaGetSymbolAddress((void**)&ff1h, g_ff1h);
    cudaGetSymbolAddress((void**)&ff1l, g_ff1l);
    cudaGetSymbolAddress((void**)&w1h,  g_w1t_h);
    cudaGetSymbolAddress((void**)&w1l,  g_w1t_l);
    cudaGetSymbolAddress((void**)&w2h,  g_w2t_h);
    cudaGetSymbolAddress((void**)&w2l,  g_w2t_l);

    const int GEMM_SMEM = 3 * STG_BYTES;   // 96 KB
    cudaFuncSetAttribute(gemm_mma<true>,  cudaFuncAttributeMaxDynamicSharedMemorySize, GEMM_SMEM);
    cudaFuncSetAttribute(gemm_mma<false>, cudaFuncAttributeMaxDynamicSharedMemorySize, GEMM_SMEM);

    // 1) prep: fold w_v; transpose+convert FFN weights to K-major bf16 hi/lo
    fold_wv_kernel<<<(EMB * 64 + 255) / 256, 256>>>(w_v);
    transpose_cvt<<<dim3(HID / 32, EMB / 32), dim3(32, 32)>>>(w_ff1, w1h, w1l, EMB, HID);
    transpose_cvt<<<dim3(EMB / 32, HID / 32), dim3(32, 32)>>>(w_ff2, w2h, w2l, HID, EMB);

    // 2) Vsum = x @ Wvs
    sgemm_n64<<<dim3(1, NTOK / 64), 256>>>(x, vsum, NTOK, EMB);

    // 3) A = Vsum.view(1024,1024) @ w_o + b_o
    sgemm128<false, true, false><<<dim3(EMB / 128, 1024 / 128), 256>>>(
        vsum, w_o, b_o, nullptr, A, 1024, EMB, EMB);

    // 4) h1 = LN1(x + A[n, l%256])  (+ bf16 hi/lo)
    ln1_kernel<<<NTOK, 256>>>(x, ln1_w, ln1_b);

    // 5) ff1 = relu(h1 @ w_ff1 + b_ff1) -> bf16 hi/lo   [HMMA]
    gemm_mma<true><<<dim3(HID / 128, NTOK / 128), 256, GEMM_SMEM>>>(
        h1h, h1l, w1h, w1l, b_ff1, nullptr, ff1h, ff1l, nullptr, EMB, HID);

    // 6) y = ff1 @ w_ff2 + b_ff2 + h1 -> fp32            [HMMA]
    gemm_mma<false><<<dim3(EMB / 128, NTOK / 128), 256, GEMM_SMEM>>>(
        ff1h, ff1l, w2h, w2l, b_ff2, h1, nullptr, nullptr, y, HID, EMB);

    // 7) out = LN2(y)
    ln2_kernel<<<NTOK, 256>>>(ln2_w, ln2_b, out);
}

// round 6
// speedup vs baseline: 2.4121x; 1.0364x over previous
#include <cuda_runtime.h>
#include <cuda_bf16.h>
#include <cstdint>
#include <math.h>

#define NB   4
#define SEQ  4096
#define EMB  1024
#define HID  4096
#define NTOK (NB * SEQ)   // 16384

// ======================= helpers ==============================================
__device__ __forceinline__ uint32_t smem_u32(const void* p) {
    uint32_t a;
    asm("{ .reg .u64 t; cvta.to.shared.u64 t, %1; cvt.u32.u64 %0, t; }" : "=r"(a) : "l"(p));
    return a;
}
// SW64 swizzle for 64-byte rows (conflict-free for 16B cp.async + ldmatrix)
__device__ __forceinline__ uint32_t swz64(uint32_t o) { return o ^ ((o >> 3) & 0x30); }

__device__ __forceinline__ void cp_async16(uint32_t dst, const void* src) {
    asm volatile("cp.async.cg.shared.global [%0], [%1], 16;" :: "r"(dst), "l"(src));
}
#define CP_COMMIT() asm volatile("cp.async.commit_group;" ::: "memory")
#define CP_WAIT2()  asm volatile("cp.async.wait_group 2;" ::: "memory")

__device__ __forceinline__ void ldmx4(uint32_t r[4], uint32_t addr) {
    asm volatile("ldmatrix.sync.aligned.m8n8.x4.shared.b16 {%0,%1,%2,%3}, [%4];"
                 : "=r"(r[0]), "=r"(r[1]), "=r"(r[2]), "=r"(r[3]) : "r"(addr));
}
__device__ __forceinline__ void mma16816(float d[4], const uint32_t a[4],
                                         uint32_t b0, uint32_t b1) {
    asm volatile("mma.sync.aligned.m16n8k16.row.col.f32.bf16.bf16.f32 "
                 "{%0,%1,%2,%3}, {%4,%5,%6,%7}, {%8,%9}, {%0,%1,%2,%3};"
                 : "+f"(d[0]), "+f"(d[1]), "+f"(d[2]), "+f"(d[3])
                 : "r"(a[0]), "r"(a[1]), "r"(a[2]), "r"(a[3]), "r"(b0), "r"(b1));
}

__device__ __forceinline__ void cvt_hilo(float x, __nv_bfloat16& h, __nv_bfloat16& l) {
    h = __float2bfloat16(x);
    l = __float2bfloat16(x - __bfloat162float(h));
}

// ======================= device scratch =======================================
__device__ float g_wvs [EMB * 64];
__device__ __align__(16) __nv_bfloat16 g_vsh[EMB * EMB];        // vsum hi (1024x1024 view)
__device__ __align__(16) __nv_bfloat16 g_vsl[EMB * EMB];        // vsum lo
__device__ __align__(16) __nv_bfloat16 g_woT_h[EMB * EMB];      // w_o^T hi
__device__ __align__(16) __nv_bfloat16 g_woT_l[EMB * EMB];
__device__ float g_A   [NB * 256 * EMB];
__device__ float g_h1  [(long long)NTOK * EMB];                 // fp32 residual
__device__ __align__(16) __nv_bfloat16 g_h1h[(long long)NTOK * EMB];
__device__ __align__(16) __nv_bfloat16 g_h1l[(long long)NTOK * EMB];
__device__ __align__(16) __nv_bfloat16 g_ff1h[(long long)NTOK * HID];
__device__ __align__(16) __nv_bfloat16 g_ff1l[(long long)NTOK * HID];
__device__ __align__(16) __nv_bfloat16 g_w1t_h[(long long)HID * EMB];  // w_ff1^T
__device__ __align__(16) __nv_bfloat16 g_w1t_l[(long long)HID * EMB];
__device__ __align__(16) __nv_bfloat16 g_w2t_h[(long long)EMB * HID];  // w_ff2^T
__device__ __align__(16) __nv_bfloat16 g_w2t_l[(long long)EMB * HID];
__device__ float g_y   [(long long)NTOK * EMB];

// ======================= fold w_v over heads ==================================
__global__ void fold_wv_kernel(const float* __restrict__ wv) {
    int idx = blockIdx.x * blockDim.x + threadIdx.x;
    if (idx >= EMB * 64) return;
    int e = idx >> 6, d = idx & 63;
    float s = 0.f;
#pragma unroll
    for (int j = 0; j < 16; j++) s += wv[e * EMB + j * 64 + d];
    g_wvs[idx] = s;
}

// ============== transpose + bf16 hi/lo convert: src(R,C) -> dst(C,R) ==========
__global__ void transpose_cvt(const float* __restrict__ src,
                              __nv_bfloat16* __restrict__ dh,
                              __nv_bfloat16* __restrict__ dl, int R, int C) {
    __shared__ float tile[32][33];
    int r = blockIdx.y * 32 + threadIdx.y;
    int c = blockIdx.x * 32 + threadIdx.x;
    tile[threadIdx.y][threadIdx.x] = src[(size_t)r * C + c];
    __syncthreads();
    int orow = blockIdx.x * 32 + threadIdx.y;
    int ocol = blockIdx.y * 32 + threadIdx.x;
    float v = tile[threadIdx.x][threadIdx.y];
    __nv_bfloat16 h, l;
    cvt_hilo(v, h, l);
    dh[(size_t)orow * R + ocol] = h;
    dl[(size_t)orow * R + ocol] = l;
}

// ====== Vsum = x @ Wvs : (16384,1024)@(1024,64), hi/lo bf16 out ===============
// BM=32, BK=32, 256 threads, grid 512 CTAs.
__global__ __launch_bounds__(256)
void vsum_kernel(const float* __restrict__ x) {
    __shared__ float  As[32][33];
    __shared__ float4 Bs[32][16];
    const int tid = threadIdx.x;
    const int base = blockIdx.x * 32;
    const int tx = tid & 15, ty = tid >> 4;      // cols tx*4, rows ty*2..+1
    float acc[2][4] = {};
    const int lr = tid >> 3, lc4 = (tid & 7) * 4;
    for (int k0 = 0; k0 < EMB; k0 += 32) {
        float4 a4 = *(const float4*)(x + (size_t)(base + lr) * EMB + k0 + lc4);
        As[lr][lc4 + 0] = a4.x; As[lr][lc4 + 1] = a4.y;
        As[lr][lc4 + 2] = a4.z; As[lr][lc4 + 3] = a4.w;
#pragma unroll
        for (int i = 0; i < 2; i++) {
            int f = tid * 2 + i;
            int row = f >> 4, col4 = f & 15;
            Bs[row][col4] = ((const float4*)g_wvs)[(size_t)(k0 + row) * 16 + col4];
        }
        __syncthreads();
#pragma unroll
        for (int ks = 0; ks < 32; ks++) {
            float a0 = As[ty * 2 + 0][ks];
            float a1 = As[ty * 2 + 1][ks];
            float4 b4 = Bs[ks][tx];
            acc[0][0] += a0 * b4.x; acc[0][1] += a0 * b4.y;
            acc[0][2] += a0 * b4.z; acc[0][3] += a0 * b4.w;
            acc[1][0] += a1 * b4.x; acc[1][1] += a1 * b4.y;
            acc[1][2] += a1 * b4.z; acc[1][3] += a1 * b4.w;
        }
        __syncthreads();
    }
#pragma unroll
    for (int i = 0; i < 2; i++) {
        const size_t o = (size_t)(base + ty * 2 + i) * 64 + tx * 4;
        __align__(8) __nv_bfloat16 h4[4], l4[4];
        cvt_hilo(acc[i][0], h4[0], l4[0]); cvt_hilo(acc[i][1], h4[1], l4[1]);
        cvt_hilo(acc[i][2], h4[2], l4[2]); cvt_hilo(acc[i][3], h4[3], l4[3]);
        *(uint2*)(g_vsh + o) = *(uint2*)h4;
        *(uint2*)(g_vsl + o) = *(uint2*)l4;
    }
}

// ================= HMMA bf16 hi/lo-split GEMM =================================
// C = A(M,K) @ B(N,K)^T. CTA tile 128x128x32, 8 warps (2x4), warp tile 64x32.
// 3-stage cp.async pipeline. Term-major MMA order (hh, hl, lh) so consecutive
// MMAs never share an accumulator (RAW distance 16).
// G1: out = relu(C+bias) -> bf16 hi/lo.  !G1: out = C+bias (+res if RES) -> fp32.
#define STG_BYTES 32768
template <bool G1, bool RES>
__global__ __launch_bounds__(256, 1)
void gemm_mma(const __nv_bfloat16* __restrict__ Ah, const __nv_bfloat16* __restrict__ Al,
              const __nv_bfloat16* __restrict__ Bh, const __nv_bfloat16* __restrict__ Bl,
              const float* __restrict__ bias, const float* __restrict__ res,
              __nv_bfloat16* __restrict__ Oh, __nv_bfloat16* __restrict__ Ol,
              float* __restrict__ Of, int K, int N) {
    extern __shared__ char smem[];
    const uint32_t sb = smem_u32(smem);
    const int tid  = threadIdx.x;
    const int lane = tid & 31;
    const int wid  = tid >> 5;
    const int wm = wid >> 2;          // 0..1  (64-row slab)
    const int wn = wid & 3;           // 0..3  (32-col slab)
    const int bx = blockIdx.x, by = blockIdx.y;

    // ---- loader mapping ------------------------------------------------------
    const int lr = tid >> 2, lg = tid & 3;
    const uint32_t sd0 = lr * 64 + ((lg ^ ((lr >> 1) & 3)) << 4);
    const uint32_t sd1 = (lr + 64) * 64 + ((lg ^ (((lr + 64) >> 1) & 3)) << 4);
    const size_t arow0 = (size_t)(by * 128 + lr) * K;
    const size_t arow1 = (size_t)(by * 128 + lr + 64) * K;
    const size_t brow0 = (size_t)(bx * 128 + lr) * K;
    const size_t brow1 = (size_t)(bx * 128 + lr + 64) * K;
    const int kel = lg * 8;

    const int NC = K / 32;
    auto load_stage = [&](int c, int s) {
        const uint32_t st = sb + s * STG_BYTES;
        const int kc = c * 32 + kel;
        cp_async16(st +         sd0, Ah + arow0 + kc);
        cp_async16(st +         sd1, Ah + arow1 + kc);
        cp_async16(st +  8192 + sd0, Al + arow0 + kc);
        cp_async16(st +  8192 + sd1, Al + arow1 + kc);
        cp_async16(st + 16384 + sd0, Bh + brow0 + kc);
        cp_async16(st + 16384 + sd1, Bh + brow1 + kc);
        cp_async16(st + 24576 + sd0, Bl + brow0 + kc);
        cp_async16(st + 24576 + sd1, Bl + brow1 + kc);
        CP_COMMIT();
    };

    load_stage(0, 0); load_stage(1, 1); load_stage(2, 2);

    // ---- ldmatrix lane addressing -------------------------------------------
    const int lr8 = lane & 7, l8 = (lane >> 3) & 1, l16 = (lane >> 4) & 1;
    const int frow = lr8 + l8 * 8;
    const int fkb  = l16 * 16;

    float acc[4][4][4] = {};

    for (int c = 0; c < NC; c++) {
        const int s = c % 3;
        CP_WAIT2();
        __syncthreads();
        const uint32_t st = sb + s * STG_BYTES;
#pragma unroll
        for (int ks = 0; ks < 2; ks++) {
            const int kb = ks * 32 + fkb;
            uint32_t ah[4][4], al[4][4], bh[4][2], bl[4][2];
#pragma unroll
            for (int mi = 0; mi < 4; mi++) {
                const uint32_t off = swz64((wm * 64 + mi * 16 + frow) * 64 + kb);
                ldmx4(ah[mi], st + off);
                ldmx4(al[mi], st + 8192 + off);
            }
#pragma unroll
            for (int nt = 0; nt < 2; nt++) {
                const uint32_t off = swz64((wn * 32 + nt * 16 + frow) * 64 + kb);
                uint32_t q[4];
                ldmx4(q, st + 16384 + off);
                bh[nt*2][0] = q[0]; bh[nt*2+1][0] = q[1];
                bh[nt*2][1] = q[2]; bh[nt*2+1][1] = q[3];
                ldmx4(q, st + 24576 + off);
                bl[nt*2][0] = q[0]; bl[nt*2+1][0] = q[1];
                bl[nt*2][1] = q[2]; bl[nt*2+1][1] = q[3];
            }
            // term-major: no consecutive MMAs share an accumulator
#pragma unroll
            for (int mi = 0; mi < 4; mi++)
#pragma unroll
                for (int j = 0; j < 4; j++)
                    mma16816(acc[mi][j], ah[mi], bh[j][0], bh[j][1]);
#pragma unroll
            for (int mi = 0; mi < 4; mi++)
#pragma unroll
                for (int j = 0; j < 4; j++)
                    mma16816(acc[mi][j], ah[mi], bl[j][0], bl[j][1]);
#pragma unroll
            for (int mi = 0; mi < 4; mi++)
#pragma unroll
                for (int j = 0; j < 4; j++)
                    mma16816(acc[mi][j], al[mi], bh[j][0], bh[j][1]);
        }
        __syncthreads();
        if (c + 3 < NC) load_stage(c + 3, s);
    }

    // ---- epilogue ------------------------------------------------------------
    const int g = lane >> 2, tg = lane & 3;
#pragma unroll
    for (int mi = 0; mi < 4; mi++) {
#pragma unroll
        for (int j = 0; j < 4; j++) {
            const int col = bx * 128 + wn * 32 + j * 8 + tg * 2;
            const float2 b2 = *(const float2*)(bias + col);
#pragma unroll
            for (int hrow = 0; hrow < 2; hrow++) {
                const size_t row = (size_t)(by * 128 + wm * 64 + mi * 16 + g + hrow * 8);
                float v0 = acc[mi][j][hrow * 2 + 0] + b2.x;
                float v1 = acc[mi][j][hrow * 2 + 1] + b2.y;
                if (G1) {
                    v0 = fmaxf(v0, 0.f); v1 = fmaxf(v1, 0.f);
                    __nv_bfloat16 h0, l0, h1, l1;
                    cvt_hilo(v0, h0, l0); cvt_hilo(v1, h1, l1);
                    __nv_bfloat162 hh; hh.x = h0; hh.y = h1;
                    __nv_bfloat162 ll; ll.x = l0; ll.y = l1;
                    *(__nv_bfloat162*)(Oh + row * N + col) = hh;
                    *(__nv_bfloat162*)(Ol + row * N + col) = ll;
                } else {
                    float2 o = make_float2(v0, v1);
                    if (RES) {
                        const float2 rv = *(const float2*)(res + row * N + col);
                        o.x += rv.x; o.y += rv.y;
                    }
                    *(float2*)(Of + row * N + col) = o;
                }
            }
        }
    }
}

// ======================= LayerNorm kernels ====================================
__device__ __forceinline__ void block_reduce2(float& s, float& q) {
#pragma unroll
    for (int off = 16; off; off >>= 1) {
        s += __shfl_xor_sync(0xffffffffu, s, off);
        q += __shfl_xor_sync(0xffffffffu, q, off);
    }
    __shared__ float sh_s[8], sh_q[8];
    int w = threadIdx.x >> 5;
    if ((threadIdx.x & 31) == 0) { sh_s[w] = s; sh_q[w] = q; }
    __syncthreads();
    s = 0.f; q = 0.f;
#pragma unroll
    for (int i = 0; i < 8; i++) { s += sh_s[i]; q += sh_q[i]; }
}

__global__ void ln1_kernel(const float* __restrict__ x,
                           const float* __restrict__ w, const float* __restrict__ b) {
    int t = blockIdx.x;
    int n = t >> 12, l = t & (SEQ - 1);
    int c = threadIdx.x;
    float4 xv = ((const float4*)(x + (size_t)t * EMB))[c];
    float4 av = ((const float4*)(g_A + (size_t)(n * 256 + (l & 255)) * EMB))[c];
    float v0 = xv.x + av.x, v1 = xv.y + av.y, v2 = xv.z + av.z, v3 = xv.w + av.w;
    float s = v0 + v1 + v2 + v3;
    float q = v0 * v0 + v1 * v1 + v2 * v2 + v3 * v3;
    block_reduce2(s, q);
    float mu  = s * (1.f / EMB);
    float var = q * (1.f / EMB) - mu * mu;
    float rs  = rsqrtf(var + 1e-5f);
    float4 wv = ((const float4*)w)[c], bv = ((const float4*)b)[c];
    float4 o;
    o.x = (v0 - mu) * rs * wv.x + bv.x;
    o.y = (v1 - mu) * rs * wv.y + bv.y;
    o.z = (v2 - mu) * rs * wv.z + bv.z;
    o.w = (v3 - mu) * rs * wv.w + bv.w;
    ((float4*)(g_h1 + (size_t)t * EMB))[c] = o;
    __align__(8) __nv_bfloat16 h4[4], l4[4];
    cvt_hilo(o.x, h4[0], l4[0]); cvt_hilo(o.y, h4[1], l4[1]);
    cvt_hilo(o.z, h4[2], l4[2]); cvt_hilo(o.w, h4[3], l4[3]);
    ((uint2*)(g_h1h + (size_t)t * EMB))[c] = *(uint2*)h4;
    ((uint2*)(g_h1l + (size_t)t * EMB))[c] = *(uint2*)l4;
}

__global__ void ln2_kernel(const float* __restrict__ w, const float* __restrict__ b,
                           float* __restrict__ out) {
    int t = blockIdx.x;
    int c = threadIdx.x;
    float4 yv = ((const float4*)(g_y + (size_t)t * EMB))[c];
    float v0 = yv.x, v1 = yv.y, v2 = yv.z, v3 = yv.w;
    float s = v0 + v1 + v2 + v3;
    float q = v0 * v0 + v1 * v1 + v2 * v2 + v3 * v3;
    block_reduce2(s, q);
    float mu  = s * (1.f / EMB);
    float var = q * (1.f / EMB) - mu * mu;
    float rs  = rsqrtf(var + 1e-5f);
    float4 wv = ((const float4*)w)[c], bv = ((const float4*)b)[c];
    float4 o;
    o.x = (v0 - mu) * rs * wv.x + bv.x;
    o.y = (v1 - mu) * rs * wv.y + bv.y;
    o.z = (v2 - mu) * rs * wv.z + bv.z;
    o.w = (v3 - mu) * rs * wv.w + bv.w;
    ((float4*)(out + (size_t)t * EMB))[c] = o;
}

// ==============================================================================
extern "C" void kernel_launch(void* const* d_in, const int* in_sizes, int n_in,
                              void* d_out, int out_size) {
    const float* x     = (const float*)d_in[0];
    const float* w_v   = (const float*)d_in[3];
    const float* w_o   = (const float*)d_in[4];
    const float* b_o   = (const float*)d_in[5];
    const float* ln1_w = (const float*)d_in[6];
    const float* ln1_b = (const float*)d_in[7];
    const float* ln2_w = (const float*)d_in[8];
    const float* ln2_b = (const float*)d_in[9];
    const float* w_ff1 = (const float*)d_in[10];
    const float* b_ff1 = (const float*)d_in[11];
    const float* w_ff2 = (const float*)d_in[12];
    const float* b_ff2 = (const float*)d_in[13];
    float* out = (float*)d_out;

    float *A, *h1, *y;
    __nv_bfloat16 *vsh, *vsl, *woh, *wol, *h1h, *h1l, *ff1h, *ff1l, *w1h, *w1l, *w2h, *w2l;
    cudaGetSymbolAddress((void**)&A,    g_A);
    cudaGetSymbolAddress((void**)&h1,   g_h1);
    cudaGetSymbolAddress((void**)&y,    g_y);
    cudaGetSymbolAddress((void**)&vsh,  g_vsh);
    cudaGetSymbolAddress((void**)&vsl,  g_vsl);
    cudaGetSymbolAddress((void**)&woh,  g_woT_h);
    cudaGetSymbolAddress((void**)&wol,  g_woT_l);
    cudaGetSymbolAddress((void**)&h1h,  g_h1h);
    cudaGetSymbolAddress((void**)&h1l,  g_h1l);
    cudaGetSymbolAddress((void**)&ff1h, g_ff1h);
    cudaGetSymbolAddress((void**)&ff1l, g_ff1l);
    cudaGetSymbolAddress((void**)&w1h,  g_w1t_h);
    cudaGetSymbolAddress((void**)&w1l,  g_w1t_l);
    cudaGetSymbolAddress((void**)&w2h,  g_w2t_h);
    cudaGetSymbolAddress((void**)&w2l,  g_w2t_l);

    const int GEMM_SMEM = 3 * STG_BYTES;   // 96 KB
    cudaFuncSetAttribute(gemm_mma<true,false>,  cudaFuncAttributeMaxDynamicSharedMemorySize, GEMM_SMEM);
    cudaFuncSetAttribute(gemm_mma<false,true>,  cudaFuncAttributeMaxDynamicSharedMemorySize, GEMM_SMEM);
    cudaFuncSetAttribute(gemm_mma<false,false>, cudaFuncAttributeMaxDynamicSharedMemorySize, GEMM_SMEM);

    // 1) prep: fold w_v; transpose+convert weights to K-major bf16 hi/lo
    fold_wv_kernel<<<(EMB * 64 + 255) / 256, 256>>>(w_v);
    transpose_cvt<<<dim3(EMB / 32, EMB / 32), dim3(32, 32)>>>(w_o,   woh, wol, EMB, EMB);
    transpose_cvt<<<dim3(HID / 32, EMB / 32), dim3(32, 32)>>>(w_ff1, w1h, w1l, EMB, HID);
    transpose_cvt<<<dim3(EMB / 32, HID / 32), dim3(32, 32)>>>(w_ff2, w2h, w2l, HID, EMB);

    // 2) Vsum = x @ Wvs -> bf16 hi/lo (1024x1024 view)
    vsum_kernel<<<NTOK / 32, 256>>>(x);

    // 3) A = Vsum @ w_o + b_o   [HMMA]
    gemm_mma<false,false><<<dim3(EMB / 128, EMB / 128), 256, GEMM_SMEM>>>(
        vsh, vsl, woh, wol, b_o, nullptr, nullptr, nullptr, A, EMB, EMB);

    // 4) h1 = LN1(x + A[n, l%256])  (+ bf16 hi/lo)
    ln1_kernel<<<NTOK, 256>>>(x, ln1_w, ln1_b);

    // 5) ff1 = relu(h1 @ w_ff1 + b_ff1) -> bf16 hi/lo   [HMMA]
    gemm_mma<true,false><<<dim3(HID / 128, NTOK / 128), 256, GEMM_SMEM>>>(
        h1h, h1l, w1h, w1l, b_ff1, nullptr, ff1h, ff1l, nullptr, EMB, HID);

    // 6) y = ff1 @ w_ff2 + b_ff2 + h1 -> fp32            [HMMA]
    gemm_mma<false,true><<<dim3(EMB / 128, NTOK / 128), 256, GEMM_SMEM>>>(
        ff1h, ff1l, w2h, w2l, b_ff2, h1, nullptr, nullptr, y, HID, EMB);

    // 7) out = LN2(y)
    ln2_kernel<<<NTOK, 256>>>(ln2_w, ln2_b, out);
}

// round 7
// speedup vs baseline: 6.3481x; 2.6317x over previous
#include <cuda_runtime.h>
#include <cuda_fp16.h>
#include <cstdint>
#include <math.h>

#define NB   4
#define SEQ  4096
#define EMB  1024
#define HID  4096
#define NTOK (NB * SEQ)   // 16384

// ======================= helpers ==============================================
__device__ __forceinline__ uint32_t smem_u32(const void* p) {
    uint32_t a;
    asm("{ .reg .u64 t; cvta.to.shared.u64 t, %1; cvt.u32.u64 %0, t; }" : "=r"(a) : "l"(p));
    return a;
}
// SW64 swizzle for 64-byte rows (conflict-free for 16B cp.async + ldmatrix)
__device__ __forceinline__ uint32_t swz64(uint32_t o) { return o ^ ((o >> 3) & 0x30); }

__device__ __forceinline__ void cp_async16(uint32_t dst, const void* src) {
    asm volatile("cp.async.cg.shared.global [%0], [%1], 16;" :: "r"(dst), "l"(src));
}
#define CP_COMMIT() asm volatile("cp.async.commit_group;" ::: "memory")
#define CP_WAIT3()  asm volatile("cp.async.wait_group 3;" ::: "memory")

__device__ __forceinline__ void ldmx4(uint32_t r[4], uint32_t addr) {
    asm volatile("ldmatrix.sync.aligned.m8n8.x4.shared.b16 {%0,%1,%2,%3}, [%4];"
                 : "=r"(r[0]), "=r"(r[1]), "=r"(r[2]), "=r"(r[3]) : "r"(addr));
}
__device__ __forceinline__ void mma16816(float d[4], const uint32_t a[4],
                                         uint32_t b0, uint32_t b1) {
    asm volatile("mma.sync.aligned.m16n8k16.row.col.f32.f16.f16.f32 "
                 "{%0,%1,%2,%3}, {%4,%5,%6,%7}, {%8,%9}, {%0,%1,%2,%3};"
                 : "+f"(d[0]), "+f"(d[1]), "+f"(d[2]), "+f"(d[3])
                 : "r"(a[0]), "r"(a[1]), "r"(a[2]), "r"(a[3]), "r"(b0), "r"(b1));
}

// ======================= device scratch =======================================
__device__ float g_wvs [EMB * 64];
__device__ __align__(16) __half g_vsh [EMB * EMB];              // vsum fp16 (1024x1024 view)
__device__ __align__(16) __half g_woT [EMB * EMB];              // w_o^T fp16
__device__ float g_A   [NB * 256 * EMB];
__device__ float g_h1  [(long long)NTOK * EMB];                 // fp32 residual
__device__ __align__(16) __half g_h1f [(long long)NTOK * EMB];  // h1 fp16
__device__ __align__(16) __half g_ff1 [(long long)NTOK * HID];  // relu(ff1) fp16
__device__ __align__(16) __half g_w1t [(long long)HID * EMB];   // w_ff1^T fp16
__device__ __align__(16) __half g_w2t [(long long)EMB * HID];   // w_ff2^T fp16
__device__ float g_y   [(long long)NTOK * EMB];

// ======================= fold w_v over heads ==================================
__global__ void fold_wv_kernel(const float* __restrict__ wv) {
    int idx = blockIdx.x * blockDim.x + threadIdx.x;
    if (idx >= EMB * 64) return;
    int e = idx >> 6, d = idx & 63;
    float s = 0.f;
#pragma unroll
    for (int j = 0; j < 16; j++) s += wv[e * EMB + j * 64 + d];
    g_wvs[idx] = s;
}

// ============== transpose + fp16 convert: src(R,C) -> dst(C,R) ================
__global__ void transpose_cvt(const float* __restrict__ src,
                              __half* __restrict__ dst, int R, int C) {
    __shared__ float tile[32][33];
    int r = blockIdx.y * 32 + threadIdx.y;
    int c = blockIdx.x * 32 + threadIdx.x;
    tile[threadIdx.y][threadIdx.x] = src[(size_t)r * C + c];
    __syncthreads();
    int orow = blockIdx.x * 32 + threadIdx.y;
    int ocol = blockIdx.y * 32 + threadIdx.x;
    dst[(size_t)orow * R + ocol] = __float2half(tile[threadIdx.x][threadIdx.y]);
}

// ====== Vsum = x @ Wvs : (16384,1024)@(1024,64), fp16 out =====================
__global__ __launch_bounds__(256)
void vsum_kernel(const float* __restrict__ x) {
    __shared__ float  As[32][33];
    __shared__ float4 Bs[32][16];
    const int tid = threadIdx.x;
    const int base = blockIdx.x * 32;
    const int tx = tid & 15, ty = tid >> 4;
    float acc[2][4] = {};
    const int lr = tid >> 3, lc4 = (tid & 7) * 4;
    for (int k0 = 0; k0 < EMB; k0 += 32) {
        float4 a4 = *(const float4*)(x + (size_t)(base + lr) * EMB + k0 + lc4);
        As[lr][lc4 + 0] = a4.x; As[lr][lc4 + 1] = a4.y;
        As[lr][lc4 + 2] = a4.z; As[lr][lc4 + 3] = a4.w;
#pragma unroll
        for (int i = 0; i < 2; i++) {
            int f = tid * 2 + i;
            int row = f >> 4, col4 = f & 15;
            Bs[row][col4] = ((const float4*)g_wvs)[(size_t)(k0 + row) * 16 + col4];
        }
        __syncthreads();
#pragma unroll
        for (int ks = 0; ks < 32; ks++) {
            float a0 = As[ty * 2 + 0][ks];
            float a1 = As[ty * 2 + 1][ks];
            float4 b4 = Bs[ks][tx];
            acc[0][0] += a0 * b4.x; acc[0][1] += a0 * b4.y;
            acc[0][2] += a0 * b4.z; acc[0][3] += a0 * b4.w;
            acc[1][0] += a1 * b4.x; acc[1][1] += a1 * b4.y;
            acc[1][2] += a1 * b4.z; acc[1][3] += a1 * b4.w;
        }
        __syncthreads();
    }
#pragma unroll
    for (int i = 0; i < 2; i++) {
        const size_t o = (size_t)(base + ty * 2 + i) * 64 + tx * 4;
        __align__(8) __half h4[4];
        h4[0] = __float2half(acc[i][0]); h4[1] = __float2half(acc[i][1]);
        h4[2] = __float2half(acc[i][2]); h4[3] = __float2half(acc[i][3]);
        *(uint2*)(g_vsh + o) = *(uint2*)h4;
    }
}

// ================= HMMA fp16 GEMM =============================================
// C = A(M,K) @ B(N,K)^T, fp16 inputs, fp32 accum. CTA tile 128x128x32,
// 8 warps (2x4), warp tile 64x32. 4-stage cp.async pipeline, 16KB/stage.
// G1: out = relu(C+bias) -> fp16.  !G1: out = C+bias (+res if RES) -> fp32.
#define STG_BYTES 16384
template <bool G1, bool RES>
__global__ __launch_bounds__(256)
void gemm_mma(const __half* __restrict__ A, const __half* __restrict__ B,
              const float* __restrict__ bias, const float* __restrict__ res,
              __half* __restrict__ Oh, float* __restrict__ Of, int K, int N) {
    extern __shared__ char smem[];
    const uint32_t sb = smem_u32(smem);
    const int tid  = threadIdx.x;
    const int lane = tid & 31;
    const int wid  = tid >> 5;
    const int wm = wid >> 2;          // 0..1  (64-row slab)
    const int wn = wid & 3;           // 0..3  (32-col slab)
    const int bx = blockIdx.x, by = blockIdx.y;

    // ---- loader mapping: per 8KB array, thread stores rows lr, lr+64 --------
    const int lr = tid >> 2, lg = tid & 3;
    const uint32_t sd0 = lr * 64 + ((lg ^ ((lr >> 1) & 3)) << 4);
    const uint32_t sd1 = (lr + 64) * 64 + ((lg ^ (((lr + 64) >> 1) & 3)) << 4);
    const size_t arow0 = (size_t)(by * 128 + lr) * K;
    const size_t arow1 = (size_t)(by * 128 + lr + 64) * K;
    const size_t brow0 = (size_t)(bx * 128 + lr) * K;
    const size_t brow1 = (size_t)(bx * 128 + lr + 64) * K;
    const int kel = lg * 8;

    const int NC = K / 32;
    auto load_stage = [&](int c, int s) {
        const uint32_t st = sb + s * STG_BYTES;
        const int kc = c * 32 + kel;
        cp_async16(st +        sd0, A + arow0 + kc);
        cp_async16(st +        sd1, A + arow1 + kc);
        cp_async16(st + 8192 + sd0, B + brow0 + kc);
        cp_async16(st + 8192 + sd1, B + brow1 + kc);
        CP_COMMIT();
    };

    load_stage(0, 0); load_stage(1, 1); load_stage(2, 2); load_stage(3, 3);

    // ---- ldmatrix lane addressing -------------------------------------------
    const int lr8 = lane & 7, l8 = (lane >> 3) & 1, l16 = (lane >> 4) & 1;
    const int frow = lr8 + l8 * 8;
    const int fkb  = l16 * 16;

    float acc[4][4][4] = {};

    for (int c = 0; c < NC; c++) {
        const int s = c & 3;
        CP_WAIT3();
        __syncthreads();
        const uint32_t st = sb + s * STG_BYTES;
#pragma unroll
        for (int ks = 0; ks < 2; ks++) {
            const int kb = ks * 32 + fkb;
            uint32_t ah[4][4], b[4][2];
#pragma unroll
            for (int mi = 0; mi < 4; mi++) {
                const uint32_t off = swz64((wm * 64 + mi * 16 + frow) * 64 + kb);
                ldmx4(ah[mi], st + off);
            }
#pragma unroll
            for (int nt = 0; nt < 2; nt++) {
                const uint32_t off = swz64((wn * 32 + nt * 16 + frow) * 64 + kb);
                uint32_t q[4];
                ldmx4(q, st + 8192 + off);
                b[nt*2][0] = q[0]; b[nt*2+1][0] = q[1];
                b[nt*2][1] = q[2]; b[nt*2+1][1] = q[3];
            }
#pragma unroll
            for (int mi = 0; mi < 4; mi++)
#pragma unroll
                for (int j = 0; j < 4; j++)
                    mma16816(acc[mi][j], ah[mi], b[j][0], b[j][1]);
        }
        __syncthreads();
        if (c + 4 < NC) load_stage(c + 4, s);
    }

    // ---- epilogue ------------------------------------------------------------
    const int g = lane >> 2, tg = lane & 3;
#pragma unroll
    for (int mi = 0; mi < 4; mi++) {
#pragma unroll
        for (int j = 0; j < 4; j++) {
            const int col = bx * 128 + wn * 32 + j * 8 + tg * 2;
            const float2 b2 = *(const float2*)(bias + col);
#pragma unroll
            for (int hrow = 0; hrow < 2; hrow++) {
                const size_t row = (size_t)(by * 128 + wm * 64 + mi * 16 + g + hrow * 8);
                float v0 = acc[mi][j][hrow * 2 + 0] + b2.x;
                float v1 = acc[mi][j][hrow * 2 + 1] + b2.y;
                if (G1) {
                    v0 = fmaxf(v0, 0.f); v1 = fmaxf(v1, 0.f);
                    __half2 hh;
                    hh.x = __float2half(v0); hh.y = __float2half(v1);
                    *(__half2*)(Oh + row * N + col) = hh;
                } else {
                    float2 o = make_float2(v0, v1);
                    if (RES) {
                        const float2 rv = *(const float2*)(res + row * N + col);
                        o.x += rv.x; o.y += rv.y;
                    }
                    *(float2*)(Of + row * N + col) = o;
                }
            }
        }
    }
}

// ======================= LayerNorm kernels ====================================
__device__ __forceinline__ void block_reduce2(float& s, float& q) {
#pragma unroll
    for (int off = 16; off; off >>= 1) {
        s += __shfl_xor_sync(0xffffffffu, s, off);
        q += __shfl_xor_sync(0xffffffffu, q, off);
    }
    __shared__ float sh_s[8], sh_q[8];
    int w = threadIdx.x >> 5;
    if ((threadIdx.x & 31) == 0) { sh_s[w] = s; sh_q[w] = q; }
    __syncthreads();
    s = 0.f; q = 0.f;
#pragma unroll
    for (int i = 0; i < 8; i++) { s += sh_s[i]; q += sh_q[i]; }
}

__global__ void ln1_kernel(const float* __restrict__ x,
                           const float* __restrict__ w, const float* __restrict__ b) {
    int t = blockIdx.x;
    int n = t >> 12, l = t & (SEQ - 1);
    int c = threadIdx.x;
    float4 xv = ((const float4*)(x + (size_t)t * EMB))[c];
    float4 av = ((const float4*)(g_A + (size_t)(n * 256 + (l & 255)) * EMB))[c];
    float v0 = xv.x + av.x, v1 = xv.y + av.y, v2 = xv.z + av.z, v3 = xv.w + av.w;
    float s = v0 + v1 + v2 + v3;
    float q = v0 * v0 + v1 * v1 + v2 * v2 + v3 * v3;
    block_reduce2(s, q);
    float mu  = s * (1.f / EMB);
    float var = q * (1.f / EMB) - mu * mu;
    float rs  = rsqrtf(var + 1e-5f);
    float4 wv = ((const float4*)w)[c], bv = ((const float4*)b)[c];
    float4 o;
    o.x = (v0 - mu) * rs * wv.x + bv.x;
    o.y = (v1 - mu) * rs * wv.y + bv.y;
    o.z = (v2 - mu) * rs * wv.z + bv.z;
    o.w = (v3 - mu) * rs * wv.w + bv.w;
    ((float4*)(g_h1 + (size_t)t * EMB))[c] = o;
    __align__(8) __half h4[4];
    h4[0] = __float2half(o.x); h4[1] = __float2half(o.y);
    h4[2] = __float2half(o.z); h4[3] = __float2half(o.w);
    ((uint2*)(g_h1f + (size_t)t * EMB))[c] = *(uint2*)h4;
}

__global__ void ln2_kernel(const float* __restrict__ w, const float* __restrict__ b,
                           float* __restrict__ out) {
    int t = blockIdx.x;
    int c = threadIdx.x;
    float4 yv = ((const float4*)(g_y + (size_t)t * EMB))[c];
    float v0 = yv.x, v1 = yv.y, v2 = yv.z, v3 = yv.w;
    float s = v0 + v1 + v2 + v3;
    float q = v0 * v0 + v1 * v1 + v2 * v2 + v3 * v3;
    block_reduce2(s, q);
    float mu  = s * (1.f / EMB);
    float var = q * (1.f / EMB) - mu * mu;
    float rs  = rsqrtf(var + 1e-5f);
    float4 wv = ((const float4*)w)[c], bv = ((const float4*)b)[c];
    float4 o;
    o.x = (v0 - mu) * rs * wv.x + bv.x;
    o.y = (v1 - mu) * rs * wv.y + bv.y;
    o.z = (v2 - mu) * rs * wv.z + bv.z;
    o.w = (v3 - mu) * rs * wv.w + bv.w;
    ((float4*)(out + (size_t)t * EMB))[c] = o;
}

// ==============================================================================
extern "C" void kernel_launch(void* const* d_in, const int* in_sizes, int n_in,
                              void* d_out, int out_size) {
    const float* x     = (const float*)d_in[0];
    const float* w_v   = (const float*)d_in[3];
    const float* w_o   = (const float*)d_in[4];
    const float* b_o   = (const float*)d_in[5];
    const float* ln1_w = (const float*)d_in[6];
    const float* ln1_b = (const float*)d_in[7];
    const float* ln2_w = (const float*)d_in[8];
    const float* ln2_b = (const float*)d_in[9];
    const float* w_ff1 = (const float*)d_in[10];
    const float* b_ff1 = (const float*)d_in[11];
    const float* w_ff2 = (const float*)d_in[12];
    const float* b_ff2 = (const float*)d_in[13];
    float* out = (float*)d_out;

    float *A, *h1, *y;
    __half *vsh, *woT, *h1f, *ff1, *w1t, *w2t;
    cudaGetSymbolAddress((void**)&A,   g_A);
    cudaGetSymbolAddress((void**)&h1,  g_h1);
    cudaGetSymbolAddress((void**)&y,   g_y);
    cudaGetSymbolAddress((void**)&vsh, g_vsh);
    cudaGetSymbolAddress((void**)&woT, g_woT);
    cudaGetSymbolAddress((void**)&h1f, g_h1f);
    cudaGetSymbolAddress((void**)&ff1, g_ff1);
    cudaGetSymbolAddress((void**)&w1t, g_w1t);
    cudaGetSymbolAddress((void**)&w2t, g_w2t);

    const int GEMM_SMEM = 4 * STG_BYTES;   // 64 KB
    cudaFuncSetAttribute(gemm_mma<true,false>,  cudaFuncAttributeMaxDynamicSharedMemorySize, GEMM_SMEM);
    cudaFuncSetAttribute(gemm_mma<false,true>,  cudaFuncAttributeMaxDynamicSharedMemorySize, GEMM_SMEM);
    cudaFuncSetAttribute(gemm_mma<false,false>, cudaFuncAttributeMaxDynamicSharedMemorySize, GEMM_SMEM);

    // 1) prep: fold w_v; transpose+convert weights to K-major fp16
    fold_wv_kernel<<<(EMB * 64 + 255) / 256, 256>>>(w_v);
    transpose_cvt<<<dim3(EMB / 32, EMB / 32), dim3(32, 32)>>>(w_o,   woT, EMB, EMB);
    transpose_cvt<<<dim3(HID / 32, EMB / 32), dim3(32, 32)>>>(w_ff1, w1t, EMB, HID);
    transpose_cvt<<<dim3(EMB / 32, HID / 32), dim3(32, 32)>>>(w_ff2, w2t, HID, EMB);

    // 2) Vsum = x @ Wvs -> fp16 (1024x1024 view)
    vsum_kernel<<<NTOK / 32, 256>>>(x);

    // 3) A = Vsum @ w_o + b_o   [HMMA fp16]
    gemm_mma<false,false><<<dim3(EMB / 128, EMB / 128), 256, GEMM_SMEM>>>(
        vsh, woT, b_o, nullptr, nullptr, A, EMB, EMB);

    // 4) h1 = LN1(x + A[n, l%256])  (+ fp16 copy)
    ln1_kernel<<<NTOK, 256>>>(x, ln1_w, ln1_b);

    // 5) ff1 = relu(h1 @ w_ff1 + b_ff1) -> fp16   [HMMA fp16]
    gemm_mma<true,false><<<dim3(HID / 128, NTOK / 128), 256, GEMM_SMEM>>>(
        h1f, w1t, b_ff1, nullptr, ff1, nullptr, EMB, HID);

    // 6) y = ff1 @ w_ff2 + b_ff2 + h1 -> fp32      [HMMA fp16]
    gemm_mma<false,true><<<dim3(EMB / 128, NTOK / 128), 256, GEMM_SMEM>>>(
        ff1, w2t, b_ff2, h1, nullptr, y, HID, EMB);

    // 7) out = LN2(y)
    ln2_kernel<<<NTOK, 256>>>(ln2_w, ln2_b, out);
}